// round 15
// baseline (speedup 1.0000x reference)
#include <cuda_runtime.h>

#define LBL 32
#define WPB 8   // warps per block

typedef unsigned long long u64;

// Static device scratch (allocation-free per harness rules).
__device__ __align__(16) float g_A[16384 * LBL];
__device__ __align__(16) float g_B[2048 * LBL];
__device__ __align__(16) float g_C[256 * LBL];
__device__ __align__(16) float g_D[32 * LBL];

// Grid barrier state (re-entrant across graph replays).
__device__ unsigned g_bar_count = 0;
__device__ unsigned g_bar_phase = 0;

__device__ __forceinline__ void grid_barrier(unsigned nblocks, unsigned& myphase) {
    __syncthreads();
    if (threadIdx.x == 0) {
        __threadfence();
        unsigned arr = atomicAdd(&g_bar_count, 1u);
        if (arr == nblocks - 1u) {
            g_bar_count = 0;
            __threadfence();
            atomicAdd(&g_bar_phase, 1u);
        } else {
            while (*(volatile unsigned*)&g_bar_phase == myphase)
                __nanosleep(64);
        }
    }
    __syncthreads();
    myphase++;
}

// Warp max of f32 via monotone int map + redux.sync.max.s32 (1 instruction).
__device__ __forceinline__ float warp_fmax1(float x) {
    int b = __float_as_int(x);
    int key = b ^ ((b >> 31) & 0x7fffffff);
    int r;
    asm("redux.sync.max.s32 %0, %1, 0xffffffff;" : "=r"(r) : "r"(key));
    return __int_as_float(r ^ ((r >> 31) & 0x7fffffff));
}

__device__ __forceinline__ u64 pack2(float a, float b) {
    u64 r; asm("mov.b64 %0, {%1,%2};" : "=l"(r) : "f"(a), "f"(b)); return r;
}

// HALF-ROW expT in registers (16 regs instead of 32):
//   rTa = expT[lane,   0:16]  (8 b64)
//   rTb = expT[lane^16, 16:32] (8 b64)
// A dot is recombined across the lane pair with one shfl_xor(16).
__device__ __forceinline__ void load_expT_half(u64 rTa[8], u64 rTb[8],
                                               const float* __restrict__ trans,
                                               int lane) {
    #pragma unroll
    for (int j = 0; j < 4; j++) {
        float4 v = ((const float4*)trans)[lane * 8 + j];
        rTa[2 * j]     = pack2(__expf(v.x), __expf(v.y));
        rTa[2 * j + 1] = pack2(__expf(v.z), __expf(v.w));
    }
    int l2 = lane ^ 16;
    #pragma unroll
    for (int j = 4; j < 8; j++) {
        float4 v = ((const float4*)trans)[l2 * 8 + j];
        rTb[2 * (j - 4)]     = pack2(__expf(v.x), __expf(v.y));
        rTb[2 * (j - 4) + 1] = pack2(__expf(v.z), __expf(v.w));
    }
}

// dot(expT[lane,:], prow[0..31]) via two half-dots + lane-pair recombine:
//   pA[l] = sum_{m<16}  expT[l,m]    * e[m]
//   pB[l] = sum_{m>=16} expT[l^16,m] * e[m]
//   dot[l] = pA[l] + pB[l^16]
// 8 broadcast LDS.128 + 16 FFMA2 (two independent chains) + 1 SHFL + adds.
__device__ __forceinline__ float dot2h(const float* __restrict__ prow,
                                       const u64 rTa[8], const u64 rTb[8]) {
    const ulonglong2* p2 = (const ulonglong2*)prow;
    u64 aA = 0ull, aB = 0ull;
    #pragma unroll
    for (int j = 0; j < 4; j++) {
        ulonglong2 v = p2[j];
        asm("fma.rn.f32x2 %0, %1, %2, %0;" : "+l"(aA) : "l"(rTa[2 * j]),     "l"(v.x));
        asm("fma.rn.f32x2 %0, %1, %2, %0;" : "+l"(aA) : "l"(rTa[2 * j + 1]), "l"(v.y));
    }
    #pragma unroll
    for (int j = 0; j < 4; j++) {
        ulonglong2 v = p2[4 + j];
        asm("fma.rn.f32x2 %0, %1, %2, %0;" : "+l"(aB) : "l"(rTb[2 * j]),     "l"(v.x));
        asm("fma.rn.f32x2 %0, %1, %2, %0;" : "+l"(aB) : "l"(rTb[2 * j + 1]), "l"(v.y));
    }
    float a, b, c, d;
    asm("mov.b64 {%0,%1}, %2;" : "=f"(a), "=f"(b) : "l"(aA));
    asm("mov.b64 {%0,%1}, %2;" : "=f"(c), "=f"(d) : "l"(aB));
    float pB = c + d;
    float pBx = __shfl_xor_sync(0xffffffffu, pB, 16);
    return (a + b) + pBx;
}

// Single-node compute (stage 3 / tail).
__device__ __forceinline__ float node_core(
    float lv, float rv, float emv, int lane,
    float* __restrict__ stg2, const u64 rTa[8], const u64 rTb[8])
{
    float ml = warp_fmax1(lv);
    float mr = warp_fmax1(rv);
    stg2[lane]       = __expf(lv - ml);
    stg2[LBL + lane] = __expf(rv - mr);
    __syncwarp();
    float res = emv + ml + mr +
                __logf(dot2h(stg2, rTa, rTb) * dot2h(stg2 + LBL, rTa, rTb));
    __syncwarp();
    return res;
}

// Two independent nodes interleaved (overlapping latency chains).
__device__ __forceinline__ void node_pair(
    float lv0, float rv0, float ev0,
    float lv1, float rv1, float ev1,
    int lane, float* __restrict__ stg4,
    const u64 rTa[8], const u64 rTb[8],
    float& r0, float& r1)
{
    float ml0 = warp_fmax1(lv0);
    float mr0 = warp_fmax1(rv0);
    float ml1 = warp_fmax1(lv1);
    float mr1 = warp_fmax1(rv1);
    stg4[lane]           = __expf(lv0 - ml0);
    stg4[LBL + lane]     = __expf(rv0 - mr0);
    stg4[2 * LBL + lane] = __expf(lv1 - ml1);
    stg4[3 * LBL + lane] = __expf(rv1 - mr1);
    __syncwarp();
    float d0 = dot2h(stg4, rTa, rTb)           * dot2h(stg4 + LBL, rTa, rTb);
    float d1 = dot2h(stg4 + 2 * LBL, rTa, rTb) * dot2h(stg4 + 3 * LBL, rTa, rTb);
    r0 = ev0 + ml0 + mr0 + __logf(d0);
    r1 = ev1 + ml1 + mr1 + __logf(d1);
    __syncwarp();
}

// ---- cp.async helpers -----------------------------------------------------
__device__ __forceinline__ void cp16(float* smem_dst, const float* gmem_src) {
    unsigned sa = (unsigned)__cvta_generic_to_shared(smem_dst);
    asm volatile("cp.async.cg.shared.global [%0], [%1], 16;"
                 :: "r"(sa), "l"(gmem_src));
}
#define CP_COMMIT() asm volatile("cp.async.commit_group;")
#define CP_WAIT1()  asm volatile("cp.async.wait_group 1;" ::: "memory")
#define CP_WAIT0()  asm volatile("cp.async.wait_group 0;" ::: "memory")

// Prefetch one slab: 64 child rows -> cb, 32 em1 + 16 em2 + 8 em3 rows -> eb.
__device__ __forceinline__ void prefetch_slab(
    float* __restrict__ cb, float* __restrict__ eb,
    const float* __restrict__ child,
    const float* __restrict__ em1, const float* __restrict__ em2,
    const float* __restrict__ em3, int s, int tid)
{
    const float* sc = child + (size_t)(s * 64) * LBL;     // 512 x 16B
    #pragma unroll
    for (int i = 0; i < 2; i++)
        cp16(cb + (tid + i * 256) * 4, sc + (tid + i * 256) * 4);
    const float* s1p = em1 + (size_t)(s * 32) * LBL;      // 256 x 16B
    cp16(eb + tid * 4, s1p + tid * 4);
    if (tid < 128) {                                      // 128 x 16B
        const float* s2p = em2 + (size_t)(s * 16) * LBL;
        cp16(eb + 32 * LBL + tid * 4, s2p + tid * 4);
    }
    if (tid < 64) {                                       // 64 x 16B
        const float* s3p = em3 + (size_t)(s * 8) * LBL;
        cp16(eb + 48 * LBL + tid * 4, s3p + tid * 4);
    }
}

// ---------------------------------------------------------------------------
// Persistent kernel: all levels in one launch. Slab = 32 nodes at level V
// -> 16 -> 8 through shared memory, slab inputs prefetched via cp.async
// double-buffer. Half-row expT keeps regs <= 64 -> 4 CTA/SM.
// ---------------------------------------------------------------------------
__global__ void __launch_bounds__(WPB * 32, 4)
persistent_kernel(const float* __restrict__ emissions,
                  const float* __restrict__ trans,
                  float* __restrict__ d_out,
                  int n_leaves)
{
    __shared__ __align__(16) float s1[32 * LBL];
    __shared__ __align__(16) float s2[16 * LBL];
    __shared__ __align__(16) float stg[WPB][4 * LBL];
    __shared__ __align__(16) float cbuf[2][64 * LBL];   // child double buffer
    __shared__ __align__(16) float ebuf[2][56 * LBL];   // em1(32)+em2(16)+em3(8)

    int tid  = threadIdx.x;
    int lane = tid & 31;
    int w    = tid >> 5;
    unsigned nblocks = gridDim.x;
    unsigned myphase = *(volatile unsigned*)&g_bar_phase;

    u64 rTa[8], rTb[8];
    load_expT_half(rTa, rTb, trans, lane);

    float* bufs[4] = { g_A, g_B, g_C, g_D };
    const float* child = emissions + (size_t)(n_leaves - 1) * LBL;  // leaves

    int V = n_leaves / 2;
    int bi = 0;
    while (V >= 128) {
        float* out = bufs[bi++];
        const float* em1 = emissions + (size_t)(V - 1) * LBL;
        const float* em2 = emissions + (size_t)(V / 2 - 1) * LBL;
        const float* em3 = emissions + (size_t)(V / 4 - 1) * LBL;
        int nslabs = V / 32;

        int s = blockIdx.x;
        int idx = 0;
        if (s < nslabs)
            prefetch_slab(cbuf[0], ebuf[0], child, em1, em2, em3, s, tid);
        CP_COMMIT();

        for (; s < nslabs; s += nblocks) {
            int sn = s + nblocks;
            if (sn < nslabs)
                prefetch_slab(cbuf[idx ^ 1], ebuf[idx ^ 1], child,
                              em1, em2, em3, sn, tid);
            CP_COMMIT();
            CP_WAIT1();          // current slab's data landed
            __syncthreads();

            const float* cb = cbuf[idx];
            const float* eb = ebuf[idx];

            // ---- Stage 1: 32 nodes, 2 pairs per warp, all from smem.
            #pragma unroll
            for (int t = 0; t < 2; t++) {
                int a0 = (2 * t) * WPB + w, a1 = (2 * t + 1) * WPB + w;
                float lv0 = cb[(2 * a0) * LBL + lane];
                float rv0 = cb[(2 * a0 + 1) * LBL + lane];
                float ev0 = eb[a0 * LBL + lane];
                float lv1 = cb[(2 * a1) * LBL + lane];
                float rv1 = cb[(2 * a1 + 1) * LBL + lane];
                float ev1 = eb[a1 * LBL + lane];
                float r0, r1;
                node_pair(lv0, rv0, ev0, lv1, rv1, ev1, lane, stg[w],
                          rTa, rTb, r0, r1);
                s1[a0 * LBL + lane] = r0;
                s1[a1 * LBL + lane] = r1;
            }
            __syncthreads();

            // ---- Stage 2: 16 nodes, one pair per warp.
            {
                int a0 = w, a1 = WPB + w;
                float lv0 = s1[2 * a0 * LBL + lane];
                float rv0 = s1[(2 * a0 + 1) * LBL + lane];
                float ev0 = eb[(32 + a0) * LBL + lane];
                float lv1 = s1[2 * a1 * LBL + lane];
                float rv1 = s1[(2 * a1 + 1) * LBL + lane];
                float ev1 = eb[(32 + a1) * LBL + lane];
                float r0, r1;
                node_pair(lv0, rv0, ev0, lv1, rv1, ev1, lane, stg[w],
                          rTa, rTb, r0, r1);
                s2[a0 * LBL + lane] = r0;
                s2[a1 * LBL + lane] = r1;
            }
            __syncthreads();

            // ---- Stage 3: 8 nodes, one per warp -> global.
            {
                int n = w;
                float lv = s2[2 * n * LBL + lane];
                float rv = s2[(2 * n + 1) * LBL + lane];
                float ev = eb[(48 + n) * LBL + lane];
                float r = node_core(lv, rv, ev, lane, stg[w], rTa, rTb);
                out[(size_t)(s * 8 + n) * LBL + lane] = r;
            }
            __syncthreads();   // protects s1/s2/cbuf/ebuf reuse next iteration

            idx ^= 1;
        }

        CP_WAIT0();
        grid_barrier(nblocks, myphase);
        child = out;
        V >>= 3;
    }

    // ---- Tail: remaining levels (V=16..1), block 0 only, direct loads.
    if (blockIdx.x == 0) {
        const float* c = child;
        float* o = s1;
        for (int v = V; v >= 1; v >>= 1) {
            const float* em = emissions + (size_t)(v - 1) * LBL;
            for (int n = w; n < v; n += WPB) {
                float lv = c[(size_t)(2 * n) * LBL + lane];
                float rv = c[(size_t)(2 * n) * LBL + LBL + lane];
                float ev = em[(size_t)n * LBL + lane];
                float r = node_core(lv, rv, ev, lane, stg[w], rTa, rTb);
                if (v > 1) o[n * LBL + lane] = r;
                else       d_out[lane] = r;
            }
            __syncthreads();
            c = o;
            o = (o == s1) ? s2 : s1;   // v<=16 fits in s2
        }
    }
}

// ---------------------------------------------------------------------------
// One graph node. Grid sized so ALL blocks are simultaneously resident.
// ---------------------------------------------------------------------------
extern "C" void kernel_launch(void* const* d_in, const int* in_sizes, int n_in,
                              void* d_out, int out_size)
{
    const float* emissions = (const float*)d_in[0];
    const float* trans     = (const float*)d_in[1];
    float* out = (float*)d_out;

    int n_nodes  = in_sizes[0] / LBL;
    int n_leaves = (n_nodes + 1) / 2;

    static int grid = 0;
    if (grid == 0) {
        int dev = 0, sms = 0, perSM = 0;
        cudaGetDevice(&dev);
        cudaDeviceGetAttribute(&sms, cudaDevAttrMultiProcessorCount, dev);
        cudaOccupancyMaxActiveBlocksPerMultiprocessor(
            &perSM, persistent_kernel, WPB * 32, 0);
        if (perSM < 1) perSM = 1;
        grid = sms * perSM;
        int maxSlabs = (n_leaves / 2) / 32;
        if (grid > maxSlabs) grid = maxSlabs;
        if (grid < 1) grid = 1;
    }

    persistent_kernel<<<grid, WPB * 32>>>(emissions, trans, out, n_leaves);
}

// round 16
// speedup vs baseline: 1.1624x; 1.1624x over previous
#include <cuda_runtime.h>

#define LBL 32
#define WPB 8   // warps per block

typedef unsigned long long u64;

// Static device scratch (allocation-free per harness rules).
__device__ __align__(16) float g_A[16384 * LBL];
__device__ __align__(16) float g_B[2048 * LBL];
__device__ __align__(16) float g_C[256 * LBL];
__device__ __align__(16) float g_D[32 * LBL];

// Grid barrier state (re-entrant across graph replays).
__device__ unsigned g_bar_count = 0;
__device__ unsigned g_bar_phase = 0;

__device__ __forceinline__ void grid_barrier(unsigned nblocks, unsigned& myphase) {
    __syncthreads();
    if (threadIdx.x == 0) {
        __threadfence();
        unsigned arr = atomicAdd(&g_bar_count, 1u);
        if (arr == nblocks - 1u) {
            g_bar_count = 0;
            __threadfence();
            atomicAdd(&g_bar_phase, 1u);
        } else {
            while (*(volatile unsigned*)&g_bar_phase == myphase)
                __nanosleep(64);
        }
    }
    __syncthreads();
    myphase++;
}

// Warp max of f32 via monotone int map + redux.sync.max.s32 (1 instruction).
__device__ __forceinline__ float warp_fmax1(float x) {
    int b = __float_as_int(x);
    int key = b ^ ((b >> 31) & 0x7fffffff);
    int r;
    asm("redux.sync.max.s32 %0, %1, 0xffffffff;" : "=r"(r) : "r"(key));
    return __int_as_float(r ^ ((r >> 31) & 0x7fffffff));
}

__device__ __forceinline__ u64 pack2(float a, float b) {
    u64 r; asm("mov.b64 %0, {%1,%2};" : "=l"(r) : "f"(a), "f"(b)); return r;
}

// expT row of this lane, packed as 16 x (f32,f32) in b64 registers.
__device__ __forceinline__ void load_expT2(u64 rT2[16],
                                           const float* __restrict__ trans,
                                           int lane) {
    #pragma unroll
    for (int j = 0; j < 8; j++) {
        float4 v = ((const float4*)trans)[lane * 8 + j];
        rT2[2 * j]     = pack2(__expf(v.x), __expf(v.y));
        rT2[2 * j + 1] = pack2(__expf(v.z), __expf(v.w));
    }
}

// dot(expT[lane,:], prow[0..31]): 8 broadcast LDS.128 + 16 packed FFMA2.
__device__ __forceinline__ float dot2s(const float* __restrict__ prow,
                                       const u64 rT2[16]) {
    const ulonglong2* p2 = (const ulonglong2*)prow;
    u64 acc0 = 0ull, acc1 = 0ull;
    #pragma unroll
    for (int j = 0; j < 8; j++) {
        ulonglong2 v = p2[j];
        asm("fma.rn.f32x2 %0, %1, %2, %0;" : "+l"(acc0) : "l"(rT2[2 * j]),     "l"(v.x));
        asm("fma.rn.f32x2 %0, %1, %2, %0;" : "+l"(acc1) : "l"(rT2[2 * j + 1]), "l"(v.y));
    }
    float a, b, c, d;
    asm("mov.b64 {%0,%1}, %2;" : "=f"(a), "=f"(b) : "l"(acc0));
    asm("mov.b64 {%0,%1}, %2;" : "=f"(c), "=f"(d) : "l"(acc1));
    return (a + b) + (c + d);
}

// Single-node compute (stage 3 / tail).
__device__ __forceinline__ float node_core(
    float lv, float rv, float emv, int lane,
    float* __restrict__ stg2, const u64 rT2[16])
{
    float ml = warp_fmax1(lv);
    float mr = warp_fmax1(rv);
    stg2[lane]       = __expf(lv - ml);
    stg2[LBL + lane] = __expf(rv - mr);
    __syncwarp();
    float res = emv + ml + mr + __logf(dot2s(stg2, rT2) * dot2s(stg2 + LBL, rT2));
    __syncwarp();
    return res;
}

// Two independent nodes interleaved (overlapping latency chains).
__device__ __forceinline__ void node_pair(
    float lv0, float rv0, float ev0,
    float lv1, float rv1, float ev1,
    int lane, float* __restrict__ stg4, const u64 rT2[16],
    float& r0, float& r1)
{
    float ml0 = warp_fmax1(lv0);
    float mr0 = warp_fmax1(rv0);
    float ml1 = warp_fmax1(lv1);
    float mr1 = warp_fmax1(rv1);
    stg4[lane]           = __expf(lv0 - ml0);
    stg4[LBL + lane]     = __expf(rv0 - mr0);
    stg4[2 * LBL + lane] = __expf(lv1 - ml1);
    stg4[3 * LBL + lane] = __expf(rv1 - mr1);
    __syncwarp();
    float d0 = dot2s(stg4, rT2)           * dot2s(stg4 + LBL, rT2);
    float d1 = dot2s(stg4 + 2 * LBL, rT2) * dot2s(stg4 + 3 * LBL, rT2);
    r0 = ev0 + ml0 + mr0 + __logf(d0);
    r1 = ev1 + ml1 + mr1 + __logf(d1);
    __syncwarp();
}

// ---- cp.async helpers -----------------------------------------------------
__device__ __forceinline__ void cp16(float* smem_dst, const float* gmem_src) {
    unsigned sa = (unsigned)__cvta_generic_to_shared(smem_dst);
    asm volatile("cp.async.cg.shared.global [%0], [%1], 16;"
                 :: "r"(sa), "l"(gmem_src));
}
#define CP_COMMIT() asm volatile("cp.async.commit_group;")
#define CP_WAIT0()  asm volatile("cp.async.wait_group 0;" ::: "memory")

// Prefetch one slab: 64 child rows -> cb, 32 em1 + 16 em2 + 8 em3 rows -> eb.
__device__ __forceinline__ void prefetch_slab(
    float* __restrict__ cb, float* __restrict__ eb,
    const float* __restrict__ child,
    const float* __restrict__ em1, const float* __restrict__ em2,
    const float* __restrict__ em3, int s, int tid)
{
    const float* sc = child + (size_t)(s * 64) * LBL;     // 512 x 16B
    #pragma unroll
    for (int i = 0; i < 2; i++)
        cp16(cb + (tid + i * 256) * 4, sc + (tid + i * 256) * 4);
    const float* s1p = em1 + (size_t)(s * 32) * LBL;      // 256 x 16B
    cp16(eb + tid * 4, s1p + tid * 4);
    if (tid < 128) {                                      // 128 x 16B
        const float* s2p = em2 + (size_t)(s * 16) * LBL;
        cp16(eb + 32 * LBL + tid * 4, s2p + tid * 4);
    }
    if (tid < 64) {                                       // 64 x 16B
        const float* s3p = em3 + (size_t)(s * 8) * LBL;
        cp16(eb + 48 * LBL + tid * 4, s3p + tid * 4);
    }
}

// ---------------------------------------------------------------------------
// Persistent kernel. Slab = 32 nodes at level V -> 16 -> 8, but with
// SUBTREE-LOCAL warp assignment: warp w computes stage-1 nodes 4w..4w+3,
// stage-2 nodes 2w,2w+1 (children = its own stage-1 registers), stage-3
// node w (children = its own stage-2 registers). No inter-stage smem, no
// inter-stage __syncthreads — one sync per slab, merged into the cp.async
// double-buffer handoff.
// ---------------------------------------------------------------------------
__global__ void __launch_bounds__(WPB * 32, 3)
persistent_kernel(const float* __restrict__ emissions,
                  const float* __restrict__ trans,
                  float* __restrict__ d_out,
                  int n_leaves)
{
    __shared__ __align__(16) float sa_[32 * LBL];       // tail only
    __shared__ __align__(16) float sb_[16 * LBL];       // tail only
    __shared__ __align__(16) float stg[WPB][4 * LBL];
    __shared__ __align__(16) float cbuf[2][64 * LBL];   // child double buffer
    __shared__ __align__(16) float ebuf[2][56 * LBL];   // em1(32)+em2(16)+em3(8)

    int tid  = threadIdx.x;
    int lane = tid & 31;
    int w    = tid >> 5;
    unsigned nblocks = gridDim.x;
    unsigned myphase = *(volatile unsigned*)&g_bar_phase;

    u64 rT2[16];
    load_expT2(rT2, trans, lane);

    float* bufs[4] = { g_A, g_B, g_C, g_D };
    const float* child = emissions + (size_t)(n_leaves - 1) * LBL;  // leaves

    int V = n_leaves / 2;
    int bi = 0;
    while (V >= 128) {
        float* out = bufs[bi++];
        const float* em1 = emissions + (size_t)(V - 1) * LBL;
        const float* em2 = emissions + (size_t)(V / 2 - 1) * LBL;
        const float* em3 = emissions + (size_t)(V / 4 - 1) * LBL;
        int nslabs = V / 32;

        int s = blockIdx.x;
        int idx = 0;
        if (s < nslabs)
            prefetch_slab(cbuf[0], ebuf[0], child, em1, em2, em3, s, tid);
        CP_COMMIT();

        for (; s < nslabs; s += nblocks) {
            CP_WAIT0();          // slab s landed in cbuf/ebuf[idx]
            __syncthreads();     // + all threads done reading buf[idx^1]

            int sn = s + nblocks;
            if (sn < nslabs)
                prefetch_slab(cbuf[idx ^ 1], ebuf[idx ^ 1], child,
                              em1, em2, em3, sn, tid);
            CP_COMMIT();

            const float* cb = cbuf[idx];
            const float* eb = ebuf[idx];

            // ---- Stage 1: warp w computes nodes 4w..4w+3 (two pairs).
            float r0, r1, r2, r3;
            {
                float lv0 = cb[(8 * w + 0) * LBL + lane];
                float rv0 = cb[(8 * w + 1) * LBL + lane];
                float ev0 = eb[(4 * w + 0) * LBL + lane];
                float lv1 = cb[(8 * w + 2) * LBL + lane];
                float rv1 = cb[(8 * w + 3) * LBL + lane];
                float ev1 = eb[(4 * w + 1) * LBL + lane];
                node_pair(lv0, rv0, ev0, lv1, rv1, ev1, lane, stg[w], rT2, r0, r1);

                float lv2 = cb[(8 * w + 4) * LBL + lane];
                float rv2 = cb[(8 * w + 5) * LBL + lane];
                float ev2 = eb[(4 * w + 2) * LBL + lane];
                float lv3 = cb[(8 * w + 6) * LBL + lane];
                float rv3 = cb[(8 * w + 7) * LBL + lane];
                float ev3 = eb[(4 * w + 3) * LBL + lane];
                node_pair(lv2, rv2, ev2, lv3, rv3, ev3, lane, stg[w], rT2, r2, r3);
            }

            // ---- Stage 2: nodes 2w,2w+1; children are r0..r3 (registers).
            float q0, q1;
            {
                float ev0 = eb[(32 + 2 * w)     * LBL + lane];
                float ev1 = eb[(32 + 2 * w + 1) * LBL + lane];
                node_pair(r0, r1, ev0, r2, r3, ev1, lane, stg[w], rT2, q0, q1);
            }

            // ---- Stage 3: node w; children q0,q1 (registers) -> global.
            {
                float ev = eb[(48 + w) * LBL + lane];
                float r = node_core(q0, q1, ev, lane, stg[w], rT2);
                out[(size_t)(s * 8 + w) * LBL + lane] = r;
            }

            idx ^= 1;
        }

        CP_WAIT0();
        grid_barrier(nblocks, myphase);
        child = out;
        V >>= 3;
    }

    // ---- Tail: remaining levels (V=16..1), block 0 only, direct loads.
    if (blockIdx.x == 0) {
        const float* c = child;
        float* o = sa_;
        for (int v = V; v >= 1; v >>= 1) {
            const float* em = emissions + (size_t)(v - 1) * LBL;
            for (int n = w; n < v; n += WPB) {
                float lv = c[(size_t)(2 * n) * LBL + lane];
                float rv = c[(size_t)(2 * n) * LBL + LBL + lane];
                float ev = em[(size_t)n * LBL + lane];
                float r = node_core(lv, rv, ev, lane, stg[w], rT2);
                if (v > 1) o[n * LBL + lane] = r;
                else       d_out[lane] = r;
            }
            __syncthreads();
            c = o;
            o = (o == sa_) ? sb_ : sa_;   // v<=16 fits in sb_
        }
    }
}

// ---------------------------------------------------------------------------
// One graph node. Grid sized so ALL blocks are simultaneously resident.
// ---------------------------------------------------------------------------
extern "C" void kernel_launch(void* const* d_in, const int* in_sizes, int n_in,
                              void* d_out, int out_size)
{
    const float* emissions = (const float*)d_in[0];
    const float* trans     = (const float*)d_in[1];
    float* out = (float*)d_out;

    int n_nodes  = in_sizes[0] / LBL;
    int n_leaves = (n_nodes + 1) / 2;

    static int grid = 0;
    if (grid == 0) {
        int dev = 0, sms = 0, perSM = 0;
        cudaGetDevice(&dev);
        cudaDeviceGetAttribute(&sms, cudaDevAttrMultiProcessorCount, dev);
        cudaOccupancyMaxActiveBlocksPerMultiprocessor(
            &perSM, persistent_kernel, WPB * 32, 0);
        if (perSM < 1) perSM = 1;
        grid = sms * perSM;
        int maxSlabs = (n_leaves / 2) / 32;
        if (grid > maxSlabs) grid = maxSlabs;
        if (grid < 1) grid = 1;
    }

    persistent_kernel<<<grid, WPB * 32>>>(emissions, trans, out, n_leaves);
}